// round 2
// baseline (speedup 1.0000x reference)
#include <cuda_runtime.h>
#include <cuda_bf16.h>
#include <math.h>

// ---------------------------------------------------------------------------
// FABlock2D: B=4, NY=NX=128, DIM=256, HEADS=8, DH=64, BOT=256, HID=1024,
// DOUT=256. fp32 baseline. Algebraic simplification: mean commuted ahead of
// the pooling projections. All kernels use <=48KB static smem (no
// cudaFuncSetAttribute needed). Scratch lives in one liveness-packed arena.
// ---------------------------------------------------------------------------

#define NB   4
#define NGR  128     // NY == NX
#define DIMC 256
#define HEADS 8
#define DH   64
#define ROWS_ALL (NB*NGR*NGR)   // 65536

// ------------------------- scratch (device globals) ------------------------
// Arena regions (element offsets), liveness-checked against the launch order:
//   un   [0,        16777216)   live steps 1-7
//   v    [16777216, 50331648)   live step 7 only
//   vt   [50331648, 83886080)   live steps 7-8
//   uphi [0,        33554432)   live steps 8-9   (un,v dead)
//   gn   [33554432, 67108864)   live steps 9-10  (vt dead; disjoint from uphi)
//   u2   [0,        16777216)   live step 10-end (uphi dead; disjoint from gn)
//   ln2  [16777216, 33554432)   live step 11     (disjoint from u2)
//   hid  [33554432, 100663296)  live step 11     (gn dead; disjoint from u2,ln2)
#define UN_OFF    0L
#define V_OFF     16777216L
#define VT_OFF    50331648L
#define UPHI_OFF  0L
#define GN_OFF    33554432L
#define U2_OFF    0L
#define LN2_OFF   16777216L
#define HID_OFF   33554432L
#define ARENA_ELEMS 100663296L   // ~403 MB

__device__ float g_arena[ARENA_ELEMS];
__device__ float g_meanx[NB*NGR*DIMC];
__device__ float g_meany[NB*NGR*DIMC];
__device__ float g_p    [NB*NGR*DIMC];
__device__ float g_hsm  [NB*NGR*1024];
__device__ float g_ux   [NB*NGR*DIMC];
__device__ float g_uy   [NB*NGR*DIMC];
__device__ float g_qkbuf[NB*NGR*1024];
__device__ float g_q    [NB*HEADS*NGR*DH];
__device__ float g_kk   [NB*HEADS*NGR*DH];
__device__ float g_attx [NB*HEADS*NGR*NGR];
__device__ float g_atty [NB*HEADS*NGR*NGR];

// ------------------------------- helpers -----------------------------------
__device__ __forceinline__ float gelu_tanh(float x) {
    float x3 = x * x * x;
    return 0.5f * x * (1.0f + tanhf(0.7978845608028654f * (x + 0.044715f * x3)));
}

// -------------------------------- LayerNorm --------------------------------
// one block (256 threads) per row of length 256
__global__ void ln_kernel(const float* __restrict__ x, const float* __restrict__ g,
                          const float* __restrict__ b, float* __restrict__ y, float eps) {
    long row = blockIdx.x;
    int t = threadIdx.x;
    float v = x[row * 256 + t];
    float s = v, s2 = v * v;
    #pragma unroll
    for (int o = 16; o; o >>= 1) {
        s  += __shfl_xor_sync(0xffffffffu, s,  o);
        s2 += __shfl_xor_sync(0xffffffffu, s2, o);
    }
    __shared__ float ws[8], ws2[8];
    int w = t >> 5, l = t & 31;
    if (l == 0) { ws[w] = s; ws2[w] = s2; }
    __syncthreads();
    if (w == 0) {
        float a  = (l < 8) ? ws[l]  : 0.f;
        float a2 = (l < 8) ? ws2[l] : 0.f;
        #pragma unroll
        for (int o = 4; o; o >>= 1) {
            a  += __shfl_xor_sync(0xffffffffu, a,  o);
            a2 += __shfl_xor_sync(0xffffffffu, a2, o);
        }
        if (l == 0) { ws[0] = a; ws2[0] = a2; }
    }
    __syncthreads();
    float mean = ws[0] * (1.f / 256.f);
    float var  = ws2[0] * (1.f / 256.f) - mean * mean;
    float r = rsqrtf(var + eps);
    y[row * 256 + t] = (v - mean) * r * g[t] + b[t];
}

// ------------------------- means over x / over y ----------------------------
__global__ void mean_over_x_kernel(const float* __restrict__ un, float* __restrict__ out) {
    int by = blockIdx.x;  // b*128 + y
    int c = threadIdx.x;
    const float* base = un + (long)by * NGR * DIMC + c;
    float s = 0.f;
    #pragma unroll 4
    for (int x = 0; x < NGR; x++) s += base[(long)x * DIMC];
    out[(long)by * DIMC + c] = s * (1.f / (float)NGR);
}
__global__ void mean_over_y_kernel(const float* __restrict__ un, float* __restrict__ out) {
    int bx = blockIdx.x;  // b*128 + x
    int b = bx >> 7, x = bx & 127;
    int c = threadIdx.x;
    const float* base = un + ((long)b * NGR * NGR + x) * DIMC + c;
    float s = 0.f;
    #pragma unroll 4
    for (int y = 0; y < NGR; y++) s += base[(long)y * NGR * DIMC];
    out[(long)bx * DIMC + c] = s * (1.f / (float)NGR);
}

// ----------------------------- generic SGEMM --------------------------------
// C[M,N] = A[M,K] @ B[K,N]  (+bias)(+gelu)(+residual), batched by blockIdx.z
// BM=BN=128, BK=8, 256 threads, 8x8 per-thread tile. All dims are multiples.
__global__ void sgemm_kernel(const float* __restrict__ A, const float* __restrict__ B,
                             float* __restrict__ C, int M, int N, int K,
                             long sA, long sB, long sC,
                             const float* __restrict__ bias,
                             const float* __restrict__ res, int do_gelu) {
    A += (long)blockIdx.z * sA;
    B += (long)blockIdx.z * sB;
    C += (long)blockIdx.z * sC;

    __shared__ float As[8][128];
    __shared__ float Bs[8][128];
    int tid = threadIdx.x;
    int m0 = blockIdx.y * 128;
    int n0 = blockIdx.x * 128;
    int tm = (tid >> 4) * 8;
    int tn = (tid & 15) * 8;

    int arow = tid >> 1, acol = (tid & 1) * 4;
    int brow = tid >> 6, bcol = (tid & 63) * 2;
    float acc[8][8] = {};

    for (int k0 = 0; k0 < K; k0 += 8) {
        float4 av = *(const float4*)(A + (long)(m0 + arow) * K + k0 + acol);
        As[acol + 0][arow] = av.x;
        As[acol + 1][arow] = av.y;
        As[acol + 2][arow] = av.z;
        As[acol + 3][arow] = av.w;
        float2 bv0 = *(const float2*)(B + (long)(k0 + brow)     * N + n0 + bcol);
        float2 bv1 = *(const float2*)(B + (long)(k0 + brow + 4) * N + n0 + bcol);
        Bs[brow][bcol] = bv0.x; Bs[brow][bcol + 1] = bv0.y;
        Bs[brow + 4][bcol] = bv1.x; Bs[brow + 4][bcol + 1] = bv1.y;
        __syncthreads();
        #pragma unroll
        for (int kk = 0; kk < 8; kk++) {
            float a[8], b[8];
            #pragma unroll
            for (int i = 0; i < 8; i++) a[i] = As[kk][tm + i];
            #pragma unroll
            for (int j = 0; j < 8; j++) b[j] = Bs[kk][tn + j];
            #pragma unroll
            for (int i = 0; i < 8; i++)
                #pragma unroll
                for (int j = 0; j < 8; j++)
                    acc[i][j] += a[i] * b[j];
        }
        __syncthreads();
    }
    #pragma unroll
    for (int i = 0; i < 8; i++) {
        long row = m0 + tm + i;
        #pragma unroll
        for (int j = 0; j < 8; j++) {
            int col = n0 + tn + j;
            float v = acc[i][j];
            if (bias) v += bias[col];
            if (do_gelu) v = gelu_tanh(v);
            if (res) v += res[row * (long)N + col];
            C[row * (long)N + col] = v;
        }
    }
}

// --------------------------------- RoPE ------------------------------------
// qkbuf rows (b*128+n, 1024); q/k out layout ((b*8+h)*128+n)*64+d
__global__ void rope_kernel(const float* __restrict__ qkbuf,
                            const float* __restrict__ cosv, const float* __restrict__ sinv,
                            float* __restrict__ q, float* __restrict__ k) {
    int idx = blockIdx.x * 256 + threadIdx.x;   // 262144 total
    int d = idx & 63;
    int n = (idx >> 6) & 127;
    int h = (idx >> 13) & 7;
    int b = idx >> 16;
    const float* P = qkbuf + (long)(b * 128 + n) * 1024;
    float c = cosv[n * 64 + d], s = sinv[n * 64 + d];
    int col = h * 64 + d;
    float t  = P[col];
    float rt = (d < 32) ? -P[col + 32] : P[col - 32];
    q[idx] = t * c + rt * s;
    float t2  = P[512 + col];
    float rt2 = (d < 32) ? -P[512 + col + 32] : P[512 + col - 32];
    k[idx] = t2 * c + rt2 * s;
}

// ----------------------- attention scores + softmax -------------------------
// one block per (b,h); d-chunked: static smem 32KB. 256 thr, 4x16 reg tile.
__global__ void attn_kernel(const float* __restrict__ q, const float* __restrict__ k,
                            float* __restrict__ attn) {
    __shared__ float qc[32 * 128];   // [d][n]
    __shared__ float kc[32 * 128];
    int bh = blockIdx.x;
    const float* qb = q + (long)bh * 8192;
    const float* kb = k + (long)bh * 8192;
    int tid = threadIdx.x;
    int c0 = (tid & 7) * 16;
    int r0 = (tid >> 3) * 4;
    float acc[4][16] = {};
    for (int dc = 0; dc < 64; dc += 32) {
        for (int t = tid; t < 4096; t += 256) {
            int n = t >> 5, d = t & 31;
            qc[d * 128 + n] = qb[n * 64 + dc + d];
            kc[d * 128 + n] = kb[n * 64 + dc + d];
        }
        __syncthreads();
        for (int d = 0; d < 32; d++) {
            float qv[4], kv[16];
            #pragma unroll
            for (int i = 0; i < 4; i++) qv[i] = qc[d * 128 + r0 + i];
            #pragma unroll
            for (int j = 0; j < 16; j++) kv[j] = kc[d * 128 + c0 + j];
            #pragma unroll
            for (int i = 0; i < 4; i++)
                #pragma unroll
                for (int j = 0; j < 16; j++)
                    acc[i][j] += qv[i] * kv[j];
        }
        __syncthreads();
    }
    #pragma unroll
    for (int i = 0; i < 4; i++) {
        float mx = -1e30f;
        #pragma unroll
        for (int j = 0; j < 16; j++) { acc[i][j] *= (1.f / 64.f); mx = fmaxf(mx, acc[i][j]); }
        #pragma unroll
        for (int o = 1; o < 8; o <<= 1) mx = fmaxf(mx, __shfl_xor_sync(0xffffffffu, mx, o));
        float s = 0.f;
        #pragma unroll
        for (int j = 0; j < 16; j++) { acc[i][j] = __expf(acc[i][j] - mx); s += acc[i][j]; }
        #pragma unroll
        for (int o = 1; o < 8; o <<= 1) s += __shfl_xor_sync(0xffffffffu, s, o);
        float inv = 1.f / s;
        float* op = attn + (long)bh * 16384 + (long)(r0 + i) * 128 + c0;
        #pragma unroll
        for (int j = 0; j < 16; j++) op[j] = acc[i][j] * inv;
    }
}

// ------------------------ transpose V to (b,h,y, x*64+c) --------------------
__global__ void vtrans_kernel(const float* __restrict__ v, float* __restrict__ vt) {
    long idx = (long)blockIdx.x * 256 + threadIdx.x;  // 2^25 total
    int c = (int)(idx & 63);
    int x = (int)((idx >> 6) & 127);
    int y = (int)((idx >> 13) & 127);
    int h = (int)((idx >> 20) & 7);
    int b = (int)(idx >> 23);
    vt[idx] = v[(((long)(b * 128 + y) * 128 + x) << 9) + h * 64 + c];
}

// ------------- einsum2 (k_x applied along x) fused with GroupNorm -----------
// one block per (b,h,i), 256 threads, m-chunked: static smem ~24.5KB.
// out[i,l,c] = sum_m kx[l,m] * uphi[i,m,c]; then GN over c (64) per (l).
__global__ void einsum2_gn_kernel(const float* __restrict__ kx, const float* __restrict__ uphi,
                                  float* __restrict__ gn) {
    __shared__ float kxs[128 * 33];  // [l][m-chunk] padded: no bank conflicts
    __shared__ float Us[32 * 64];    // [m-chunk][c]
    int bz = blockIdx.x;
    int i = bz & 127, h = (bz >> 7) & 7, b = bz >> 10;
    const float* kxb = kx + (long)(b * 8 + h) * 16384;
    const float* ub  = uphi + ((long)(b * 8 + h) * 128 + i) * 8192;
    int tid = threadIdx.x;
    int c0 = (tid & 15) * 4;
    int l0 = (tid >> 4) * 8;
    float acc[8][4] = {};
    for (int mc = 0; mc < 128; mc += 32) {
        for (int t = tid; t < 4096; t += 256) {
            int l = t >> 5, m = t & 31;
            kxs[l * 33 + m] = kxb[l * 128 + mc + m];
        }
        for (int t = tid; t < 2048; t += 256) Us[t] = ub[mc * 64 + t];
        __syncthreads();
        #pragma unroll 4
        for (int m = 0; m < 32; m++) {
            float a[8], bb[4];
            #pragma unroll
            for (int ii = 0; ii < 8; ii++) a[ii] = kxs[(l0 + ii) * 33 + m];
            #pragma unroll
            for (int jj = 0; jj < 4; jj++) bb[jj] = Us[m * 64 + c0 + jj];
            #pragma unroll
            for (int ii = 0; ii < 8; ii++)
                #pragma unroll
                for (int jj = 0; jj < 4; jj++)
                    acc[ii][jj] += a[ii] * bb[jj];
        }
        __syncthreads();
    }
    // GroupNorm over c: threads sharing the same l-group are the 16 lanes with
    // equal tid>>4 (contiguous, xor<16 stays in-group).
    #pragma unroll
    for (int ii = 0; ii < 8; ii++) {
        float s = 0.f, s2 = 0.f;
        #pragma unroll
        for (int jj = 0; jj < 4; jj++) { float v = acc[ii][jj]; s += v; s2 += v * v; }
        #pragma unroll
        for (int o = 1; o < 16; o <<= 1) {
            s  += __shfl_xor_sync(0xffffffffu, s,  o);
            s2 += __shfl_xor_sync(0xffffffffu, s2, o);
        }
        float mean = s * (1.f / 64.f);
        float var = fmaxf(s2 * (1.f / 64.f) - mean * mean, 0.f);
        float r = rsqrtf(var + 1e-6f);
        float* op = gn + ((long)((b * 128 + i) * 128 + (l0 + ii))) * 512 + h * 64 + c0;
        #pragma unroll
        for (int jj = 0; jj < 4; jj++) op[jj] = (acc[ii][jj] - mean) * r;
    }
}

// ------------------------------- host side ----------------------------------
static inline void launch_sgemm(const float* A, const float* B, float* C,
                                int M, int N, int K,
                                long sA, long sB, long sC, int batch,
                                const float* bias, const float* res, int do_gelu) {
    dim3 grid(N / 128, M / 128, batch);
    sgemm_kernel<<<grid, 256>>>(A, B, C, M, N, K, sA, sB, sC, bias, res, do_gelu);
}

extern "C" void kernel_launch(void* const* d_in, const int* in_sizes, int n_in,
                              void* d_out, int out_size) {
    const float* u      = (const float*)d_in[0];
    const float* cos_y  = (const float*)d_in[1];
    const float* sin_y  = (const float*)d_in[2];
    const float* cos_x  = (const float*)d_in[3];
    const float* sin_x  = (const float*)d_in[4];
    // d_in[5] scalar_cond: unused by reference
    const float* ln1_g  = (const float*)d_in[6];
    const float* ln1_b  = (const float*)d_in[7];
    const float* ln2_g  = (const float*)d_in[8];
    const float* ln2_b  = (const float*)d_in[9];
    const float* Wv     = (const float*)d_in[10];
    const float* Wy_in  = (const float*)d_in[11];
    const float* Wy1    = (const float*)d_in[12];
    const float* by1    = (const float*)d_in[13];
    const float* Wy2    = (const float*)d_in[14];
    const float* by2    = (const float*)d_in[15];
    const float* Wx_in  = (const float*)d_in[16];
    const float* Wx1    = (const float*)d_in[17];
    const float* bx1    = (const float*)d_in[18];
    const float* Wx2    = (const float*)d_in[19];
    const float* bx2    = (const float*)d_in[20];
    const float* Wqk_x  = (const float*)d_in[21];
    const float* Wqk_y  = (const float*)d_in[22];
    const float* Wm     = (const float*)d_in[23];
    const float* bm     = (const float*)d_in[24];
    const float* Wf1    = (const float*)d_in[25];
    const float* bf1    = (const float*)d_in[26];
    const float* Wf2    = (const float*)d_in[27];
    const float* bf2    = (const float*)d_in[28];
    float* out = (float*)d_out;

    float *arena, *p_meanx, *p_meany, *p_p, *p_hsm, *p_ux, *p_uy, *p_qkbuf;
    float *p_q, *p_kk, *p_attx, *p_atty;
    cudaGetSymbolAddress((void**)&arena, g_arena);
    cudaGetSymbolAddress((void**)&p_meanx, g_meanx);
    cudaGetSymbolAddress((void**)&p_meany, g_meany);
    cudaGetSymbolAddress((void**)&p_p, g_p);
    cudaGetSymbolAddress((void**)&p_hsm, g_hsm);
    cudaGetSymbolAddress((void**)&p_ux, g_ux);
    cudaGetSymbolAddress((void**)&p_uy, g_uy);
    cudaGetSymbolAddress((void**)&p_qkbuf, g_qkbuf);
    cudaGetSymbolAddress((void**)&p_q, g_q);
    cudaGetSymbolAddress((void**)&p_kk, g_kk);
    cudaGetSymbolAddress((void**)&p_attx, g_attx);
    cudaGetSymbolAddress((void**)&p_atty, g_atty);

    float* p_un   = arena + UN_OFF;
    float* p_v    = arena + V_OFF;
    float* p_vt   = arena + VT_OFF;
    float* p_uphi = arena + UPHI_OFF;
    float* p_gn   = arena + GN_OFF;
    float* p_u2   = arena + U2_OFF;
    float* p_ln2  = arena + LN2_OFF;
    float* p_hid  = arena + HID_OFF;

    // 1) LayerNorm 1
    ln_kernel<<<ROWS_ALL, 256>>>(u, ln1_g, ln1_b, p_un, 1e-5f);

    // 2) means (commuted ahead of the pooling projections — matmul is linear)
    mean_over_x_kernel<<<NB * NGR, 256>>>(p_un, p_meany);  // (b,y,c): mean over x
    mean_over_y_kernel<<<NB * NGR, 256>>>(p_un, p_meanx);  // (b,x,c): mean over y

    // 3) pooling reducer x
    launch_sgemm(p_meanx, Wx_in, p_p, 512, 256, 256, 0, 0, 0, 1, nullptr, nullptr, 0);
    launch_sgemm(p_p, Wx1, p_hsm, 512, 1024, 256, 0, 0, 0, 1, bx1, nullptr, 1);
    launch_sgemm(p_hsm, Wx2, p_ux, 512, 256, 1024, 0, 0, 0, 1, bx2, nullptr, 0);
    // 4) pooling reducer y
    launch_sgemm(p_meany, Wy_in, p_p, 512, 256, 256, 0, 0, 0, 1, nullptr, nullptr, 0);
    launch_sgemm(p_p, Wy1, p_hsm, 512, 1024, 256, 0, 0, 0, 1, by1, nullptr, 1);
    launch_sgemm(p_hsm, Wy2, p_uy, 512, 256, 1024, 0, 0, 0, 1, by2, nullptr, 0);

    // 5) dp kernel x
    launch_sgemm(p_ux, Wqk_x, p_qkbuf, 512, 1024, 256, 0, 0, 0, 1, nullptr, nullptr, 0);
    rope_kernel<<<1024, 256>>>(p_qkbuf, cos_x, sin_x, p_q, p_kk);
    attn_kernel<<<NB * HEADS, 256>>>(p_q, p_kk, p_attx);
    // 6) dp kernel y
    launch_sgemm(p_uy, Wqk_y, p_qkbuf, 512, 1024, 256, 0, 0, 0, 1, nullptr, nullptr, 0);
    rope_kernel<<<1024, 256>>>(p_qkbuf, cos_y, sin_y, p_q, p_kk);
    attn_kernel<<<NB * HEADS, 256>>>(p_q, p_kk, p_atty);

    // 7) V projection and transpose to (b,h,y, x*64+c)
    launch_sgemm(p_un, Wv, p_v, ROWS_ALL, 512, 256, 0, 0, 0, 1, nullptr, nullptr, 0);
    vtrans_kernel<<<(ROWS_ALL * 512) / 256, 256>>>(p_v, p_vt);

    // 8) einsum1: per (b,h): k_y(128x128) @ vt(128x8192) — batched GEMM
    launch_sgemm(p_atty, p_vt, p_uphi, 128, 8192, 128,
                 16384, 1048576, 1048576, NB * HEADS, nullptr, nullptr, 0);

    // 9) einsum2 (k_x along x) fused with GroupNorm -> (b,i,l,h*64+c)
    einsum2_gn_kernel<<<NB * HEADS * NGR, 256>>>(p_attx, p_uphi, p_gn);

    // 10) u2 = gn @ Wm + bm + u
    launch_sgemm(p_gn, Wm, p_u2, ROWS_ALL, 256, 512, 0, 0, 0, 1, bm, u, 0);

    // 11) LN2 + final MLP + residual
    ln_kernel<<<ROWS_ALL, 256>>>(p_u2, ln2_g, ln2_b, p_ln2, 1e-5f);
    launch_sgemm(p_ln2, Wf1, p_hid, ROWS_ALL, 1024, 256, 0, 0, 0, 1, bf1, nullptr, 1);
    launch_sgemm(p_hid, Wf2, out, ROWS_ALL, 256, 1024, 0, 0, 0, 1, bf2, p_u2, 0);

    (void)in_sizes; (void)n_in; (void)out_size;
}

// round 3
// speedup vs baseline: 2.5299x; 2.5299x over previous
#include <cuda_runtime.h>
#include <cuda_bf16.h>
#include <math.h>
#include <stdint.h>

// ---------------------------------------------------------------------------
// FABlock2D: B=4, NY=NX=128, DIM=256, HEADS=8, DH=64, BOT=256, HID=1024,
// DOUT=256. All GEMMs on tensor cores via mma.sync tf32 (fp32 accum).
// Mean commuted ahead of pooling projections. Liveness-packed arena.
// ---------------------------------------------------------------------------

#define NB   4
#define NGR  128
#define DIMC 256
#define HEADS 8
#define DH   64
#define ROWS_ALL (NB*NGR*NGR)   // 65536

// ------------------------- scratch (device globals) ------------------------
//   un   [0,        16777216)   live steps 1-7
//   v    [16777216, 50331648)   live step 7 only
//   vt   [50331648, 83886080)   live steps 7-8
//   uphi [0,        33554432)   live steps 8-9   (un,v dead)
//   gn   [33554432, 67108864)   live steps 9-10  (vt dead)
//   u2   [0,        16777216)   live step 10-end (uphi dead)
//   ln2  [16777216, 33554432)   live step 11
//   hid  [33554432, 100663296)  live step 11     (gn dead)
#define UN_OFF    0L
#define V_OFF     16777216L
#define VT_OFF    50331648L
#define UPHI_OFF  0L
#define GN_OFF    33554432L
#define U2_OFF    0L
#define LN2_OFF   16777216L
#define HID_OFF   33554432L
#define ARENA_ELEMS 100663296L

__device__ float g_arena[ARENA_ELEMS];
__device__ float g_meanx[NB*NGR*DIMC];
__device__ float g_meany[NB*NGR*DIMC];
__device__ float g_p    [NB*NGR*DIMC];
__device__ float g_hsm  [NB*NGR*1024];
__device__ float g_ux   [NB*NGR*DIMC];
__device__ float g_uy   [NB*NGR*DIMC];
__device__ float g_qkbuf[NB*NGR*1024];
__device__ float g_q    [NB*HEADS*NGR*DH];
__device__ float g_kk   [NB*HEADS*NGR*DH];
__device__ float g_attx [NB*HEADS*NGR*NGR];
__device__ float g_atty [NB*HEADS*NGR*NGR];

// ------------------------------- helpers -----------------------------------
__device__ __forceinline__ float gelu_tanh(float x) {
    float x3 = x * x * x;
    return 0.5f * x * (1.0f + tanhf(0.7978845608028654f * (x + 0.044715f * x3)));
}
__device__ __forceinline__ uint32_t f2tf32(float x) {
    uint32_t r;
    asm("cvt.rna.tf32.f32 %0, %1;" : "=r"(r) : "f"(x));
    return r;
}
__device__ __forceinline__ void mma_tf32(float c[4], const uint32_t a[4], const uint32_t b[2]) {
    asm volatile(
        "mma.sync.aligned.m16n8k8.row.col.f32.tf32.tf32.f32 "
        "{%0,%1,%2,%3}, {%4,%5,%6,%7}, {%8,%9}, {%0,%1,%2,%3};\n"
        : "+f"(c[0]), "+f"(c[1]), "+f"(c[2]), "+f"(c[3])
        : "r"(a[0]), "r"(a[1]), "r"(a[2]), "r"(a[3]), "r"(b[0]), "r"(b[1]));
}

// --------------------------- tf32 tensor-core GEMM --------------------------
// C[M,N] = A[M,K] @ B[K,N] (+bias)(+gelu)(+residual), batched via blockIdx.z.
// As stored [m][k] (stride BK+4: mma a-loads conflict-free),
// Bs stored [k][n] (stride BN+8: mma b-loads conflict-free).
template<int BM, int BN, int BK, int THREADS, int WARPS_M, int WARPS_N>
__global__ __launch_bounds__(THREADS) void tf32_gemm_kernel(
        const float* __restrict__ A, const float* __restrict__ B,
        float* __restrict__ C, int M, int N, int K,
        long sA, long sB, long sC,
        const float* __restrict__ bias, const float* __restrict__ res, int do_gelu) {
    constexpr int WM = BM / WARPS_M;          // warp tile M (mult of 16)
    constexpr int WN = BN / WARPS_N;          // warp tile N (mult of 8)
    constexpr int MI = WM / 16;
    constexpr int NI = WN / 8;
    __shared__ uint32_t As[BM][BK + 4];
    __shared__ uint32_t Bs[BK][BN + 8];

    A += (long)blockIdx.z * sA;
    B += (long)blockIdx.z * sB;
    C += (long)blockIdx.z * sC;

    int tid = threadIdx.x;
    int warp = tid >> 5, lane = tid & 31;
    int wm = warp / WARPS_N, wn = warp % WARPS_N;
    int m0 = blockIdx.y * BM, n0 = blockIdx.x * BN;
    int lg = lane >> 2, lt = lane & 3;

    float c[MI][NI][4];
    #pragma unroll
    for (int i = 0; i < MI; i++)
        #pragma unroll
        for (int j = 0; j < NI; j++)
            #pragma unroll
            for (int r = 0; r < 4; r++) c[i][j][r] = 0.f;

    for (int k0 = 0; k0 < K; k0 += BK) {
        #pragma unroll
        for (int it = 0; it < (BM * BK / 4) / THREADS; it++) {
            int v = tid + it * THREADS;
            int m = v / (BK / 4), kq = v % (BK / 4);
            float4 x = *(const float4*)(A + (long)(m0 + m) * K + k0 + kq * 4);
            As[m][kq * 4 + 0] = f2tf32(x.x);
            As[m][kq * 4 + 1] = f2tf32(x.y);
            As[m][kq * 4 + 2] = f2tf32(x.z);
            As[m][kq * 4 + 3] = f2tf32(x.w);
        }
        #pragma unroll
        for (int it = 0; it < (BK * BN / 4) / THREADS; it++) {
            int v = tid + it * THREADS;
            int k = v / (BN / 4), nq = v % (BN / 4);
            float4 x = *(const float4*)(B + (long)(k0 + k) * N + n0 + nq * 4);
            Bs[k][nq * 4 + 0] = f2tf32(x.x);
            Bs[k][nq * 4 + 1] = f2tf32(x.y);
            Bs[k][nq * 4 + 2] = f2tf32(x.z);
            Bs[k][nq * 4 + 3] = f2tf32(x.w);
        }
        __syncthreads();
        #pragma unroll
        for (int ks = 0; ks < BK / 8; ks++) {
            int kb = ks * 8;
            uint32_t af[MI][4], bf[NI][2];
            #pragma unroll
            for (int mi = 0; mi < MI; mi++) {
                int mr = wm * WM + mi * 16 + lg;
                af[mi][0] = As[mr][kb + lt];
                af[mi][1] = As[mr + 8][kb + lt];
                af[mi][2] = As[mr][kb + lt + 4];
                af[mi][3] = As[mr + 8][kb + lt + 4];
            }
            #pragma unroll
            for (int ni = 0; ni < NI; ni++) {
                int nc = wn * WN + ni * 8 + lg;
                bf[ni][0] = Bs[kb + lt][nc];
                bf[ni][1] = Bs[kb + lt + 4][nc];
            }
            #pragma unroll
            for (int mi = 0; mi < MI; mi++)
                #pragma unroll
                for (int ni = 0; ni < NI; ni++)
                    mma_tf32(c[mi][ni], af[mi], bf[ni]);
        }
        __syncthreads();
    }

    #pragma unroll
    for (int mi = 0; mi < MI; mi++) {
        #pragma unroll
        for (int ni = 0; ni < NI; ni++) {
            int col = n0 + wn * WN + ni * 8 + 2 * lt;
            float b0 = 0.f, b1 = 0.f;
            if (bias) { b0 = bias[col]; b1 = bias[col + 1]; }
            #pragma unroll
            for (int half = 0; half < 2; half++) {
                long row = m0 + wm * WM + mi * 16 + lg + half * 8;
                float v0 = c[mi][ni][half * 2 + 0] + b0;
                float v1 = c[mi][ni][half * 2 + 1] + b1;
                if (do_gelu) { v0 = gelu_tanh(v0); v1 = gelu_tanh(v1); }
                if (res) {
                    v0 += res[row * (long)N + col];
                    v1 += res[row * (long)N + col + 1];
                }
                float2 o; o.x = v0; o.y = v1;
                *(float2*)(C + row * (long)N + col) = o;
            }
        }
    }
}

// -------------------------------- LayerNorm --------------------------------
__global__ void ln_kernel(const float* __restrict__ x, const float* __restrict__ g,
                          const float* __restrict__ b, float* __restrict__ y, float eps) {
    long row = blockIdx.x;
    int t = threadIdx.x;
    float v = x[row * 256 + t];
    float s = v, s2 = v * v;
    #pragma unroll
    for (int o = 16; o; o >>= 1) {
        s  += __shfl_xor_sync(0xffffffffu, s,  o);
        s2 += __shfl_xor_sync(0xffffffffu, s2, o);
    }
    __shared__ float ws[8], ws2[8];
    int w = t >> 5, l = t & 31;
    if (l == 0) { ws[w] = s; ws2[w] = s2; }
    __syncthreads();
    if (w == 0) {
        float a  = (l < 8) ? ws[l]  : 0.f;
        float a2 = (l < 8) ? ws2[l] : 0.f;
        #pragma unroll
        for (int o = 4; o; o >>= 1) {
            a  += __shfl_xor_sync(0xffffffffu, a,  o);
            a2 += __shfl_xor_sync(0xffffffffu, a2, o);
        }
        if (l == 0) { ws[0] = a; ws2[0] = a2; }
    }
    __syncthreads();
    float mean = ws[0] * (1.f / 256.f);
    float var  = ws2[0] * (1.f / 256.f) - mean * mean;
    float r = rsqrtf(var + eps);
    y[row * 256 + t] = (v - mean) * r * g[t] + b[t];
}

// ------------------------- means over x / over y ----------------------------
__global__ void mean_over_x_kernel(const float* __restrict__ un, float* __restrict__ out) {
    int by = blockIdx.x;
    int c = threadIdx.x;
    const float* base = un + (long)by * NGR * DIMC + c;
    float s = 0.f;
    #pragma unroll 4
    for (int x = 0; x < NGR; x++) s += base[(long)x * DIMC];
    out[(long)by * DIMC + c] = s * (1.f / (float)NGR);
}
__global__ void mean_over_y_kernel(const float* __restrict__ un, float* __restrict__ out) {
    int bx = blockIdx.x;
    int b = bx >> 7, x = bx & 127;
    int c = threadIdx.x;
    const float* base = un + ((long)b * NGR * NGR + x) * DIMC + c;
    float s = 0.f;
    #pragma unroll 4
    for (int y = 0; y < NGR; y++) s += base[(long)y * NGR * DIMC];
    out[(long)bx * DIMC + c] = s * (1.f / (float)NGR);
}

// --------------------------------- RoPE ------------------------------------
__global__ void rope_kernel(const float* __restrict__ qkbuf,
                            const float* __restrict__ cosv, const float* __restrict__ sinv,
                            float* __restrict__ q, float* __restrict__ k) {
    int idx = blockIdx.x * 256 + threadIdx.x;
    int d = idx & 63;
    int n = (idx >> 6) & 127;
    int h = (idx >> 13) & 7;
    int b = idx >> 16;
    const float* P = qkbuf + (long)(b * 128 + n) * 1024;
    float c = cosv[n * 64 + d], s = sinv[n * 64 + d];
    int col = h * 64 + d;
    float t  = P[col];
    float rt = (d < 32) ? -P[col + 32] : P[col - 32];
    q[idx] = t * c + rt * s;
    float t2  = P[512 + col];
    float rt2 = (d < 32) ? -P[512 + col + 32] : P[512 + col - 32];
    k[idx] = t2 * c + rt2 * s;
}

// ----------------------- attention scores + softmax -------------------------
__global__ void attn_kernel(const float* __restrict__ q, const float* __restrict__ k,
                            float* __restrict__ attn) {
    __shared__ float qc[32 * 128];
    __shared__ float kc[32 * 128];
    int bh = blockIdx.x;
    const float* qb = q + (long)bh * 8192;
    const float* kb = k + (long)bh * 8192;
    int tid = threadIdx.x;
    int c0 = (tid & 7) * 16;
    int r0 = (tid >> 3) * 4;
    float acc[4][16] = {};
    for (int dc = 0; dc < 64; dc += 32) {
        for (int t = tid; t < 4096; t += 256) {
            int n = t >> 5, d = t & 31;
            qc[d * 128 + n] = qb[n * 64 + dc + d];
            kc[d * 128 + n] = kb[n * 64 + dc + d];
        }
        __syncthreads();
        for (int d = 0; d < 32; d++) {
            float qv[4], kv[16];
            #pragma unroll
            for (int i = 0; i < 4; i++) qv[i] = qc[d * 128 + r0 + i];
            #pragma unroll
            for (int j = 0; j < 16; j++) kv[j] = kc[d * 128 + c0 + j];
            #pragma unroll
            for (int i = 0; i < 4; i++)
                #pragma unroll
                for (int j = 0; j < 16; j++)
                    acc[i][j] += qv[i] * kv[j];
        }
        __syncthreads();
    }
    #pragma unroll
    for (int i = 0; i < 4; i++) {
        float mx = -1e30f;
        #pragma unroll
        for (int j = 0; j < 16; j++) { acc[i][j] *= (1.f / 64.f); mx = fmaxf(mx, acc[i][j]); }
        #pragma unroll
        for (int o = 1; o < 8; o <<= 1) mx = fmaxf(mx, __shfl_xor_sync(0xffffffffu, mx, o));
        float s = 0.f;
        #pragma unroll
        for (int j = 0; j < 16; j++) { acc[i][j] = __expf(acc[i][j] - mx); s += acc[i][j]; }
        #pragma unroll
        for (int o = 1; o < 8; o <<= 1) s += __shfl_xor_sync(0xffffffffu, s, o);
        float inv = 1.f / s;
        float* op = attn + (long)bh * 16384 + (long)(r0 + i) * 128 + c0;
        #pragma unroll
        for (int j = 0; j < 16; j++) op[j] = acc[i][j] * inv;
    }
}

// ------------------------ transpose V to (b,h,y, x*64+c) --------------------
__global__ void vtrans_kernel(const float* __restrict__ v, float* __restrict__ vt) {
    long idx = (long)blockIdx.x * 256 + threadIdx.x;
    int c = (int)(idx & 63);
    int x = (int)((idx >> 6) & 127);
    int y = (int)((idx >> 13) & 127);
    int h = (int)((idx >> 20) & 7);
    int b = (int)(idx >> 23);
    vt[idx] = v[(((long)(b * 128 + y) * 128 + x) << 9) + h * 64 + c];
}

// ------------- einsum2 (k_x applied along x) fused with GroupNorm -----------
__global__ void einsum2_gn_kernel(const float* __restrict__ kx, const float* __restrict__ uphi,
                                  float* __restrict__ gn) {
    __shared__ float kxs[128 * 33];
    __shared__ float Us[32 * 64];
    int bz = blockIdx.x;
    int i = bz & 127, h = (bz >> 7) & 7, b = bz >> 10;
    const float* kxb = kx + (long)(b * 8 + h) * 16384;
    const float* ub  = uphi + ((long)(b * 8 + h) * 128 + i) * 8192;
    int tid = threadIdx.x;
    int c0 = (tid & 15) * 4;
    int l0 = (tid >> 4) * 8;
    float acc[8][4] = {};
    for (int mc = 0; mc < 128; mc += 32) {
        for (int t = tid; t < 4096; t += 256) {
            int l = t >> 5, m = t & 31;
            kxs[l * 33 + m] = kxb[l * 128 + mc + m];
        }
        for (int t = tid; t < 2048; t += 256) Us[t] = ub[mc * 64 + t];
        __syncthreads();
        #pragma unroll 4
        for (int m = 0; m < 32; m++) {
            float a[8], bb[4];
            #pragma unroll
            for (int ii = 0; ii < 8; ii++) a[ii] = kxs[(l0 + ii) * 33 + m];
            #pragma unroll
            for (int jj = 0; jj < 4; jj++) bb[jj] = Us[m * 64 + c0 + jj];
            #pragma unroll
            for (int ii = 0; ii < 8; ii++)
                #pragma unroll
                for (int jj = 0; jj < 4; jj++)
                    acc[ii][jj] += a[ii] * bb[jj];
        }
        __syncthreads();
    }
    #pragma unroll
    for (int ii = 0; ii < 8; ii++) {
        float s = 0.f, s2 = 0.f;
        #pragma unroll
        for (int jj = 0; jj < 4; jj++) { float v = acc[ii][jj]; s += v; s2 += v * v; }
        #pragma unroll
        for (int o = 1; o < 16; o <<= 1) {
            s  += __shfl_xor_sync(0xffffffffu, s,  o);
            s2 += __shfl_xor_sync(0xffffffffu, s2, o);
        }
        float mean = s * (1.f / 64.f);
        float var = fmaxf(s2 * (1.f / 64.f) - mean * mean, 0.f);
        float r = rsqrtf(var + 1e-6f);
        float* op = gn + ((long)((b * 128 + i) * 128 + (l0 + ii))) * 512 + h * 64 + c0;
        #pragma unroll
        for (int jj = 0; jj < 4; jj++) op[jj] = (acc[ii][jj] - mean) * r;
    }
}

// ------------------------------- host side ----------------------------------
static inline void gemm_big(const float* A, const float* B, float* C,
                            int M, int N, int K,
                            long sA, long sB, long sC, int batch,
                            const float* bias, const float* res, int do_gelu) {
    dim3 grid(N / 128, M / 128, batch);
    tf32_gemm_kernel<128, 128, 32, 256, 2, 4><<<grid, 256>>>(
        A, B, C, M, N, K, sA, sB, sC, bias, res, do_gelu);
}
static inline void gemm_small(const float* A, const float* B, float* C,
                              int M, int N, int K,
                              const float* bias, const float* res, int do_gelu) {
    dim3 grid(N / 64, M / 64, 1);
    tf32_gemm_kernel<64, 64, 32, 128, 2, 2><<<grid, 128>>>(
        A, B, C, M, N, K, 0, 0, 0, bias, res, do_gelu);
}

extern "C" void kernel_launch(void* const* d_in, const int* in_sizes, int n_in,
                              void* d_out, int out_size) {
    const float* u      = (const float*)d_in[0];
    const float* cos_y  = (const float*)d_in[1];
    const float* sin_y  = (const float*)d_in[2];
    const float* cos_x  = (const float*)d_in[3];
    const float* sin_x  = (const float*)d_in[4];
    // d_in[5] scalar_cond: unused by reference
    const float* ln1_g  = (const float*)d_in[6];
    const float* ln1_b  = (const float*)d_in[7];
    const float* ln2_g  = (const float*)d_in[8];
    const float* ln2_b  = (const float*)d_in[9];
    const float* Wv     = (const float*)d_in[10];
    const float* Wy_in  = (const float*)d_in[11];
    const float* Wy1    = (const float*)d_in[12];
    const float* by1    = (const float*)d_in[13];
    const float* Wy2    = (const float*)d_in[14];
    const float* by2    = (const float*)d_in[15];
    const float* Wx_in  = (const float*)d_in[16];
    const float* Wx1    = (const float*)d_in[17];
    const float* bx1    = (const float*)d_in[18];
    const float* Wx2    = (const float*)d_in[19];
    const float* bx2    = (const float*)d_in[20];
    const float* Wqk_x  = (const float*)d_in[21];
    const float* Wqk_y  = (const float*)d_in[22];
    const float* Wm     = (const float*)d_in[23];
    const float* bm     = (const float*)d_in[24];
    const float* Wf1    = (const float*)d_in[25];
    const float* bf1    = (const float*)d_in[26];
    const float* Wf2    = (const float*)d_in[27];
    const float* bf2    = (const float*)d_in[28];
    float* out = (float*)d_out;

    float *arena, *p_meanx, *p_meany, *p_p, *p_hsm, *p_ux, *p_uy, *p_qkbuf;
    float *p_q, *p_kk, *p_attx, *p_atty;
    cudaGetSymbolAddress((void**)&arena, g_arena);
    cudaGetSymbolAddress((void**)&p_meanx, g_meanx);
    cudaGetSymbolAddress((void**)&p_meany, g_meany);
    cudaGetSymbolAddress((void**)&p_p, g_p);
    cudaGetSymbolAddress((void**)&p_hsm, g_hsm);
    cudaGetSymbolAddress((void**)&p_ux, g_ux);
    cudaGetSymbolAddress((void**)&p_uy, g_uy);
    cudaGetSymbolAddress((void**)&p_qkbuf, g_qkbuf);
    cudaGetSymbolAddress((void**)&p_q, g_q);
    cudaGetSymbolAddress((void**)&p_kk, g_kk);
    cudaGetSymbolAddress((void**)&p_attx, g_attx);
    cudaGetSymbolAddress((void**)&p_atty, g_atty);

    float* p_un   = arena + UN_OFF;
    float* p_v    = arena + V_OFF;
    float* p_vt   = arena + VT_OFF;
    float* p_uphi = arena + UPHI_OFF;
    float* p_gn   = arena + GN_OFF;
    float* p_u2   = arena + U2_OFF;
    float* p_ln2  = arena + LN2_OFF;
    float* p_hid  = arena + HID_OFF;

    // 1) LayerNorm 1
    ln_kernel<<<ROWS_ALL, 256>>>(u, ln1_g, ln1_b, p_un, 1e-5f);

    // 2) means (commuted ahead of the pooling projections)
    mean_over_x_kernel<<<NB * NGR, 256>>>(p_un, p_meany);
    mean_over_y_kernel<<<NB * NGR, 256>>>(p_un, p_meanx);

    // 3) pooling reducer x
    gemm_small(p_meanx, Wx_in, p_p, 512, 256, 256, nullptr, nullptr, 0);
    gemm_small(p_p, Wx1, p_hsm, 512, 1024, 256, bx1, nullptr, 1);
    gemm_small(p_hsm, Wx2, p_ux, 512, 256, 1024, bx2, nullptr, 0);
    // 4) pooling reducer y
    gemm_small(p_meany, Wy_in, p_p, 512, 256, 256, nullptr, nullptr, 0);
    gemm_small(p_p, Wy1, p_hsm, 512, 1024, 256, by1, nullptr, 1);
    gemm_small(p_hsm, Wy2, p_uy, 512, 256, 1024, by2, nullptr, 0);

    // 5) dp kernel x
    gemm_small(p_ux, Wqk_x, p_qkbuf, 512, 1024, 256, nullptr, nullptr, 0);
    rope_kernel<<<1024, 256>>>(p_qkbuf, cos_x, sin_x, p_q, p_kk);
    attn_kernel<<<NB * HEADS, 256>>>(p_q, p_kk, p_attx);
    // 6) dp kernel y
    gemm_small(p_uy, Wqk_y, p_qkbuf, 512, 1024, 256, nullptr, nullptr, 0);
    rope_kernel<<<1024, 256>>>(p_qkbuf, cos_y, sin_y, p_q, p_kk);
    attn_kernel<<<NB * HEADS, 256>>>(p_q, p_kk, p_atty);

    // 7) V projection and transpose to (b,h,y, x*64+c)
    gemm_big(p_un, Wv, p_v, ROWS_ALL, 512, 256, 0, 0, 0, 1, nullptr, nullptr, 0);
    vtrans_kernel<<<(ROWS_ALL * 512) / 256, 256>>>(p_v, p_vt);

    // 8) einsum1: per (b,h): k_y(128x128) @ vt(128x8192)
    gemm_big(p_atty, p_vt, p_uphi, 128, 8192, 128,
             16384, 1048576, 1048576, NB * HEADS, nullptr, nullptr, 0);

    // 9) einsum2 (k_x along x) fused with GroupNorm
    einsum2_gn_kernel<<<NB * HEADS * NGR, 256>>>(p_attx, p_uphi, p_gn);

    // 10) u2 = gn @ Wm + bm + u
    gemm_big(p_gn, Wm, p_u2, ROWS_ALL, 256, 512, 0, 0, 0, 1, bm, u, 0);

    // 11) LN2 + final MLP + residual
    ln_kernel<<<ROWS_ALL, 256>>>(p_u2, ln2_g, ln2_b, p_ln2, 1e-5f);
    gemm_big(p_ln2, Wf1, p_hid, ROWS_ALL, 1024, 256, 0, 0, 0, 1, bf1, nullptr, 1);
    gemm_big(p_hid, Wf2, out, ROWS_ALL, 256, 1024, 0, 0, 0, 1, bf2, p_u2, 0);

    (void)in_sizes; (void)n_in; (void)out_size;
}

// round 4
// speedup vs baseline: 3.1189x; 1.2328x over previous
#include <cuda_runtime.h>
#include <cuda_bf16.h>
#include <math.h>
#include <stdint.h>

// ---------------------------------------------------------------------------
// FABlock2D on GB300. tf32 mma.sync GEMMs with cp.async 2-stage pipeline,
// x/y dual-batched small chains, Wv epilogue fused with V transpose.
// ---------------------------------------------------------------------------

#define NB   4
#define NGR  128
#define DIMC 256
#define HEADS 8
#define DH   64
#define ROWS_ALL (NB*NGR*NGR)   // 65536

// ------------------------- scratch (device globals) ------------------------
//   un   [0,        16777216)   live steps 1-9
//   vt   [50331648, 83886080)   live steps 9-10
//   uphi [0,        33554432)   live steps 10-11  (un dead)
//   gn   [33554432, 67108864)   live steps 11-12  (vt dead before gn write)
//   u2   [0,        16777216)   live 12-end       (uphi dead)
//   ln2  [16777216, 33554432)   live step 13-14
//   hid  [33554432, 100663296)  live step 14-15   (gn dead)
#define UN_OFF    0L
#define VT_OFF    50331648L
#define UPHI_OFF  0L
#define GN_OFF    33554432L
#define U2_OFF    0L
#define LN2_OFF   16777216L
#define HID_OFF   33554432L
#define ARENA_ELEMS 100663296L

__device__ float g_arena[ARENA_ELEMS];
__device__ float g_meanx[512*256];
__device__ float g_meany[512*256];
__device__ float g_p2   [2*512*256];
__device__ float g_hsm2 [2*512*1024];
__device__ float g_ux   [512*256];
__device__ float g_uy   [512*256];
__device__ float g_qk2  [2*512*1024];
__device__ float g_q2   [2*262144];
__device__ float g_k2   [2*262144];
__device__ float g_att2 [2*524288];   // [0]=x (kx), [1]=y (ky)

// ------------------------------- helpers -----------------------------------
__device__ __forceinline__ float gelu_tanh(float x) {
    float x3 = x * x * x;
    return 0.5f * x * (1.0f + tanhf(0.7978845608028654f * (x + 0.044715f * x3)));
}
__device__ __forceinline__ uint32_t f2tf32(float x) {
    uint32_t r;
    asm("cvt.rna.tf32.f32 %0, %1;" : "=r"(r) : "f"(x));
    return r;
}
__device__ __forceinline__ void mma_tf32(float c[4], const uint32_t a[4], const uint32_t b[2]) {
    asm volatile(
        "mma.sync.aligned.m16n8k8.row.col.f32.tf32.tf32.f32 "
        "{%0,%1,%2,%3}, {%4,%5,%6,%7}, {%8,%9}, {%0,%1,%2,%3};\n"
        : "+f"(c[0]), "+f"(c[1]), "+f"(c[2]), "+f"(c[3])
        : "r"(a[0]), "r"(a[1]), "r"(a[2]), "r"(a[3]), "r"(b[0]), "r"(b[1]));
}
__device__ __forceinline__ void cp16(void* dst, const void* src) {
    uint32_t d = (uint32_t)__cvta_generic_to_shared(dst);
    asm volatile("cp.async.ca.shared.global [%0], [%1], 16;\n" :: "r"(d), "l"(src));
}

// --------------------- pipelined tf32 tensor-core GEMM ----------------------
template<int BM, int BN, int BK, int THREADS, int WARPS_M, int WARPS_N>
struct GemmSmem {
    float As[2][BM][BK + 4];
    float Bs[2][BK][BN + 8];
};

// C[M,N] = A[M,K] @ B[K,N] (+bias)(+gelu)(+res). VMAP=1: scatter C per V-layout.
template<int BM, int BN, int BK, int THREADS, int WARPS_M, int WARPS_N, int VMAP>
__device__ __forceinline__ void gemm_core(
        const float* __restrict__ A, const float* __restrict__ B, float* __restrict__ C,
        int M, int N, int K,
        const float* __restrict__ bias, const float* __restrict__ res, int do_gelu,
        GemmSmem<BM, BN, BK, THREADS, WARPS_M, WARPS_N>& sm) {
    constexpr int WM = BM / WARPS_M;
    constexpr int WN = BN / WARPS_N;
    constexpr int MI = WM / 16;
    constexpr int NI = WN / 8;
    constexpr int ITA = (BM * BK / 4) / THREADS;
    constexpr int ITB = (BK * BN / 4) / THREADS;

    int tid = threadIdx.x;
    int warp = tid >> 5, lane = tid & 31;
    int wm = warp / WARPS_N, wn = warp % WARPS_N;
    int m0 = blockIdx.y * BM, n0 = blockIdx.x * BN;
    int lg = lane >> 2, lt = lane & 3;

    float c[MI][NI][4] = {};

    auto load_stage = [&](int k0, int s) {
        #pragma unroll
        for (int it = 0; it < ITA; it++) {
            int v = tid + it * THREADS;
            int m = v / (BK / 4), kq = (v % (BK / 4)) * 4;
            cp16(&sm.As[s][m][kq], A + (long)(m0 + m) * K + k0 + kq);
        }
        #pragma unroll
        for (int it = 0; it < ITB; it++) {
            int v = tid + it * THREADS;
            int k = v / (BN / 4), nq = (v % (BN / 4)) * 4;
            cp16(&sm.Bs[s][k][nq], B + (long)(k0 + k) * N + n0 + nq);
        }
    };

    int T = K / BK;
    load_stage(0, 0);
    asm volatile("cp.async.commit_group;\n");
    for (int t = 0; t < T; t++) {
        int cur = t & 1;
        if (t + 1 < T) load_stage((t + 1) * BK, cur ^ 1);
        asm volatile("cp.async.commit_group;\n");
        asm volatile("cp.async.wait_group 1;\n");
        __syncthreads();
        #pragma unroll
        for (int ks = 0; ks < BK / 8; ks++) {
            int kb = ks * 8;
            uint32_t af[MI][4], bf[NI][2];
            #pragma unroll
            for (int mi = 0; mi < MI; mi++) {
                int mr = wm * WM + mi * 16 + lg;
                af[mi][0] = f2tf32(sm.As[cur][mr][kb + lt]);
                af[mi][1] = f2tf32(sm.As[cur][mr + 8][kb + lt]);
                af[mi][2] = f2tf32(sm.As[cur][mr][kb + lt + 4]);
                af[mi][3] = f2tf32(sm.As[cur][mr + 8][kb + lt + 4]);
            }
            #pragma unroll
            for (int ni = 0; ni < NI; ni++) {
                int nc = wn * WN + ni * 8 + lg;
                bf[ni][0] = f2tf32(sm.Bs[cur][kb + lt][nc]);
                bf[ni][1] = f2tf32(sm.Bs[cur][kb + lt + 4][nc]);
            }
            #pragma unroll
            for (int mi = 0; mi < MI; mi++)
                #pragma unroll
                for (int ni = 0; ni < NI; ni++)
                    mma_tf32(c[mi][ni], af[mi], bf[ni]);
        }
        __syncthreads();
    }

    #pragma unroll
    for (int mi = 0; mi < MI; mi++) {
        #pragma unroll
        for (int ni = 0; ni < NI; ni++) {
            int col = n0 + wn * WN + ni * 8 + 2 * lt;
            float b0 = 0.f, b1 = 0.f;
            if (bias) { b0 = bias[col]; b1 = bias[col + 1]; }
            #pragma unroll
            for (int half = 0; half < 2; half++) {
                long row = m0 + wm * WM + mi * 16 + lg + half * 8;
                float v0 = c[mi][ni][half * 2 + 0] + b0;
                float v1 = c[mi][ni][half * 2 + 1] + b1;
                if (do_gelu) { v0 = gelu_tanh(v0); v1 = gelu_tanh(v1); }
                if (res) {
                    v0 += res[row * (long)N + col];
                    v1 += res[row * (long)N + col + 1];
                }
                float2 o; o.x = v0; o.y = v1;
                if (VMAP) {
                    // row=(b*128+y)*128+x, col=h*64+c -> vt[((b*8+h)*128+y)*8192 + x*64+c]
                    int bb = (int)(row >> 14), y = (int)(row >> 7) & 127, x = (int)row & 127;
                    int h = col >> 6, cc = col & 63;
                    long off = ((long)((bb * 8 + h) * 128 + y)) * 8192 + x * 64 + cc;
                    *(float2*)(C + off) = o;
                } else {
                    *(float2*)(C + row * (long)N + col) = o;
                }
            }
        }
    }
}

template<int BM, int BN, int BK, int THREADS, int WARPS_M, int WARPS_N, int VMAP>
__global__ __launch_bounds__(THREADS) void gemm_pipe_kernel(
        const float* __restrict__ A, const float* __restrict__ B, float* __restrict__ C,
        int M, int N, int K, long sA, long sB, long sC,
        const float* __restrict__ bias, const float* __restrict__ res, int do_gelu) {
    __shared__ __align__(16) GemmSmem<BM, BN, BK, THREADS, WARPS_M, WARPS_N> sm;
    gemm_core<BM, BN, BK, THREADS, WARPS_M, WARPS_N, VMAP>(
        A + (long)blockIdx.z * sA, B + (long)blockIdx.z * sB, C + (long)blockIdx.z * sC,
        M, N, K, bias, res, do_gelu, sm);
}

// dual-pointer variant: blockIdx.z picks the x(0)/y(1) operand set
template<int BM, int BN, int BK, int THREADS, int WARPS_M, int WARPS_N>
__global__ __launch_bounds__(THREADS) void gemm_dual_kernel(
        const float* __restrict__ A0, const float* __restrict__ A1,
        const float* __restrict__ B0, const float* __restrict__ B1,
        float* __restrict__ C0, float* __restrict__ C1,
        int M, int N, int K,
        const float* __restrict__ bias0, const float* __restrict__ bias1, int do_gelu) {
    __shared__ __align__(16) GemmSmem<BM, BN, BK, THREADS, WARPS_M, WARPS_N> sm;
    bool z = blockIdx.z != 0;
    gemm_core<BM, BN, BK, THREADS, WARPS_M, WARPS_N, 0>(
        z ? A1 : A0, z ? B1 : B0, z ? C1 : C0, M, N, K,
        z ? bias1 : bias0, nullptr, do_gelu, sm);
}

// -------------------------------- LayerNorm --------------------------------
__global__ void ln_kernel(const float* __restrict__ x, const float* __restrict__ g,
                          const float* __restrict__ b, float* __restrict__ y, float eps) {
    long row = blockIdx.x;
    int t = threadIdx.x;
    float v = x[row * 256 + t];
    float s = v, s2 = v * v;
    #pragma unroll
    for (int o = 16; o; o >>= 1) {
        s  += __shfl_xor_sync(0xffffffffu, s,  o);
        s2 += __shfl_xor_sync(0xffffffffu, s2, o);
    }
    __shared__ float ws[8], ws2[8];
    int w = t >> 5, l = t & 31;
    if (l == 0) { ws[w] = s; ws2[w] = s2; }
    __syncthreads();
    if (w == 0) {
        float a  = (l < 8) ? ws[l]  : 0.f;
        float a2 = (l < 8) ? ws2[l] : 0.f;
        #pragma unroll
        for (int o = 4; o; o >>= 1) {
            a  += __shfl_xor_sync(0xffffffffu, a,  o);
            a2 += __shfl_xor_sync(0xffffffffu, a2, o);
        }
        if (l == 0) { ws[0] = a; ws2[0] = a2; }
    }
    __syncthreads();
    float mean = ws[0] * (1.f / 256.f);
    float var  = ws2[0] * (1.f / 256.f) - mean * mean;
    float r = rsqrtf(var + eps);
    y[row * 256 + t] = (v - mean) * r * g[t] + b[t];
}

// ------------------------- means over x / over y ----------------------------
__global__ void mean_over_x_kernel(const float* __restrict__ un, float* __restrict__ out) {
    int by = blockIdx.x;
    int c = threadIdx.x;
    const float* base = un + (long)by * NGR * DIMC + c;
    float s = 0.f;
    #pragma unroll 4
    for (int x = 0; x < NGR; x++) s += base[(long)x * DIMC];
    out[(long)by * DIMC + c] = s * (1.f / (float)NGR);
}
__global__ void mean_over_y_kernel(const float* __restrict__ un, float* __restrict__ out) {
    int bx = blockIdx.x;
    int b = bx >> 7, x = bx & 127;
    int c = threadIdx.x;
    const float* base = un + ((long)b * NGR * NGR + x) * DIMC + c;
    float s = 0.f;
    #pragma unroll 4
    for (int y = 0; y < NGR; y++) s += base[(long)y * NGR * DIMC];
    out[(long)bx * DIMC + c] = s * (1.f / (float)NGR);
}

// ------------------------------ RoPE (x+y) ----------------------------------
__global__ void rope2_kernel(const float* __restrict__ qk2,
                             const float* __restrict__ cx, const float* __restrict__ sx,
                             const float* __restrict__ cy, const float* __restrict__ sy,
                             float* __restrict__ q2, float* __restrict__ k2) {
    int idx = blockIdx.x * 256 + threadIdx.x;   // 524288 total
    int z = idx >> 18;
    int i = idx & 262143;
    int d = i & 63;
    int n = (i >> 6) & 127;
    int h = (i >> 13) & 7;
    int b = i >> 16;
    const float* P = qk2 + (long)z * 524288 + (long)(b * 128 + n) * 1024;
    const float* cosv = z ? cy : cx;
    const float* sinv = z ? sy : sx;
    float c = cosv[n * 64 + d], s = sinv[n * 64 + d];
    int col = h * 64 + d;
    float t  = P[col];
    float rt = (d < 32) ? -P[col + 32] : P[col - 32];
    q2[idx] = t * c + rt * s;
    float t2  = P[512 + col];
    float rt2 = (d < 32) ? -P[512 + col + 32] : P[512 + col - 32];
    k2[idx] = t2 * c + rt2 * s;
}

// ----------------------- attention scores + softmax (x+y) -------------------
__global__ void attn_kernel(const float* __restrict__ q, const float* __restrict__ k,
                            float* __restrict__ attn) {
    __shared__ float qc[32 * 128];
    __shared__ float kc[32 * 128];
    int bh = blockIdx.x;   // 0..63: [z][b][h]
    const float* qb = q + (long)bh * 8192;
    const float* kb = k + (long)bh * 8192;
    int tid = threadIdx.x;
    int c0 = (tid & 7) * 16;
    int r0 = (tid >> 3) * 4;
    float acc[4][16] = {};
    for (int dc = 0; dc < 64; dc += 32) {
        for (int t = tid; t < 4096; t += 256) {
            int n = t >> 5, d = t & 31;
            qc[d * 128 + n] = qb[n * 64 + dc + d];
            kc[d * 128 + n] = kb[n * 64 + dc + d];
        }
        __syncthreads();
        for (int d = 0; d < 32; d++) {
            float qv[4], kv[16];
            #pragma unroll
            for (int i = 0; i < 4; i++) qv[i] = qc[d * 128 + r0 + i];
            #pragma unroll
            for (int j = 0; j < 16; j++) kv[j] = kc[d * 128 + c0 + j];
            #pragma unroll
            for (int i = 0; i < 4; i++)
                #pragma unroll
                for (int j = 0; j < 16; j++)
                    acc[i][j] += qv[i] * kv[j];
        }
        __syncthreads();
    }
    #pragma unroll
    for (int i = 0; i < 4; i++) {
        float mx = -1e30f;
        #pragma unroll
        for (int j = 0; j < 16; j++) { acc[i][j] *= (1.f / 64.f); mx = fmaxf(mx, acc[i][j]); }
        #pragma unroll
        for (int o = 1; o < 8; o <<= 1) mx = fmaxf(mx, __shfl_xor_sync(0xffffffffu, mx, o));
        float s = 0.f;
        #pragma unroll
        for (int j = 0; j < 16; j++) { acc[i][j] = __expf(acc[i][j] - mx); s += acc[i][j]; }
        #pragma unroll
        for (int o = 1; o < 8; o <<= 1) s += __shfl_xor_sync(0xffffffffu, s, o);
        float inv = 1.f / s;
        float* op = attn + (long)bh * 16384 + (long)(r0 + i) * 128 + c0;
        #pragma unroll
        for (int j = 0; j < 16; j++) op[j] = acc[i][j] * inv;
    }
}

// ------------- einsum2 (k_x applied along x) fused with GroupNorm -----------
__global__ void einsum2_gn_kernel(const float* __restrict__ kx, const float* __restrict__ uphi,
                                  float* __restrict__ gn) {
    __shared__ float kxs[128 * 33];
    __shared__ float Us[32 * 64];
    int bz = blockIdx.x;
    int i = bz & 127, h = (bz >> 7) & 7, b = bz >> 10;
    const float* kxb = kx + (long)(b * 8 + h) * 16384;
    const float* ub  = uphi + ((long)(b * 8 + h) * 128 + i) * 8192;
    int tid = threadIdx.x;
    int c0 = (tid & 15) * 4;
    int l0 = (tid >> 4) * 8;
    float acc[8][4] = {};
    for (int mc = 0; mc < 128; mc += 32) {
        for (int t = tid; t < 4096; t += 256) {
            int l = t >> 5, m = t & 31;
            kxs[l * 33 + m] = kxb[l * 128 + mc + m];
        }
        for (int t = tid; t < 2048; t += 256) Us[t] = ub[mc * 64 + t];
        __syncthreads();
        #pragma unroll 4
        for (int m = 0; m < 32; m++) {
            float a[8], bb[4];
            #pragma unroll
            for (int ii = 0; ii < 8; ii++) a[ii] = kxs[(l0 + ii) * 33 + m];
            #pragma unroll
            for (int jj = 0; jj < 4; jj++) bb[jj] = Us[m * 64 + c0 + jj];
            #pragma unroll
            for (int ii = 0; ii < 8; ii++)
                #pragma unroll
                for (int jj = 0; jj < 4; jj++)
                    acc[ii][jj] += a[ii] * bb[jj];
        }
        __syncthreads();
    }
    #pragma unroll
    for (int ii = 0; ii < 8; ii++) {
        float s = 0.f, s2 = 0.f;
        #pragma unroll
        for (int jj = 0; jj < 4; jj++) { float v = acc[ii][jj]; s += v; s2 += v * v; }
        #pragma unroll
        for (int o = 1; o < 16; o <<= 1) {
            s  += __shfl_xor_sync(0xffffffffu, s,  o);
            s2 += __shfl_xor_sync(0xffffffffu, s2, o);
        }
        float mean = s * (1.f / 64.f);
        float var = fmaxf(s2 * (1.f / 64.f) - mean * mean, 0.f);
        float r = rsqrtf(var + 1e-6f);
        float* op = gn + ((long)((b * 128 + i) * 128 + (l0 + ii))) * 512 + h * 64 + c0;
        #pragma unroll
        for (int jj = 0; jj < 4; jj++) op[jj] = (acc[ii][jj] - mean) * r;
    }
}

// ------------------------------- host side ----------------------------------
static inline void gemm_big(const float* A, const float* B, float* C,
                            int M, int N, int K, long sA, long sB, long sC, int batch,
                            const float* bias, const float* res, int do_gelu) {
    dim3 grid(N / 128, M / 128, batch);
    gemm_pipe_kernel<128, 128, 16, 256, 2, 4, 0><<<grid, 256>>>(
        A, B, C, M, N, K, sA, sB, sC, bias, res, do_gelu);
}
static inline void gemm_big_vmap(const float* A, const float* B, float* C,
                                 int M, int N, int K) {
    dim3 grid(N / 128, M / 128, 1);
    gemm_pipe_kernel<128, 128, 16, 256, 2, 4, 1><<<grid, 256>>>(
        A, B, C, M, N, K, 0, 0, 0, nullptr, nullptr, 0);
}
static inline void gemm_dual(const float* A0, const float* A1,
                             const float* B0, const float* B1,
                             float* C0, float* C1, int M, int N, int K,
                             const float* bias0, const float* bias1, int do_gelu) {
    dim3 grid(N / 64, M / 64, 2);
    gemm_dual_kernel<64, 64, 32, 128, 2, 2><<<grid, 128>>>(
        A0, A1, B0, B1, C0, C1, M, N, K, bias0, bias1, do_gelu);
}

extern "C" void kernel_launch(void* const* d_in, const int* in_sizes, int n_in,
                              void* d_out, int out_size) {
    const float* u      = (const float*)d_in[0];
    const float* cos_y  = (const float*)d_in[1];
    const float* sin_y  = (const float*)d_in[2];
    const float* cos_x  = (const float*)d_in[3];
    const float* sin_x  = (const float*)d_in[4];
    // d_in[5] scalar_cond: unused by reference
    const float* ln1_g  = (const float*)d_in[6];
    const float* ln1_b  = (const float*)d_in[7];
    const float* ln2_g  = (const float*)d_in[8];
    const float* ln2_b  = (const float*)d_in[9];
    const float* Wv     = (const float*)d_in[10];
    const float* Wy_in  = (const float*)d_in[11];
    const float* Wy1    = (const float*)d_in[12];
    const float* by1    = (const float*)d_in[13];
    const float* Wy2    = (const float*)d_in[14];
    const float* by2    = (const float*)d_in[15];
    const float* Wx_in  = (const float*)d_in[16];
    const float* Wx1    = (const float*)d_in[17];
    const float* bx1    = (const float*)d_in[18];
    const float* Wx2    = (const float*)d_in[19];
    const float* bx2    = (const float*)d_in[20];
    const float* Wqk_x  = (const float*)d_in[21];
    const float* Wqk_y  = (const float*)d_in[22];
    const float* Wm     = (const float*)d_in[23];
    const float* bm     = (const float*)d_in[24];
    const float* Wf1    = (const float*)d_in[25];
    const float* bf1    = (const float*)d_in[26];
    const float* Wf2    = (const float*)d_in[27];
    const float* bf2    = (const float*)d_in[28];
    float* out = (float*)d_out;

    float *arena, *p_meanx, *p_meany, *p_p2, *p_hsm2, *p_ux, *p_uy, *p_qk2;
    float *p_q2, *p_k2, *p_att2;
    cudaGetSymbolAddress((void**)&arena, g_arena);
    cudaGetSymbolAddress((void**)&p_meanx, g_meanx);
    cudaGetSymbolAddress((void**)&p_meany, g_meany);
    cudaGetSymbolAddress((void**)&p_p2, g_p2);
    cudaGetSymbolAddress((void**)&p_hsm2, g_hsm2);
    cudaGetSymbolAddress((void**)&p_ux, g_ux);
    cudaGetSymbolAddress((void**)&p_uy, g_uy);
    cudaGetSymbolAddress((void**)&p_qk2, g_qk2);
    cudaGetSymbolAddress((void**)&p_q2, g_q2);
    cudaGetSymbolAddress((void**)&p_k2, g_k2);
    cudaGetSymbolAddress((void**)&p_att2, g_att2);

    float* p_un   = arena + UN_OFF;
    float* p_vt   = arena + VT_OFF;
    float* p_uphi = arena + UPHI_OFF;
    float* p_gn   = arena + GN_OFF;
    float* p_u2   = arena + U2_OFF;
    float* p_ln2  = arena + LN2_OFF;
    float* p_hid  = arena + HID_OFF;

    // 1) LayerNorm 1
    ln_kernel<<<ROWS_ALL, 256>>>(u, ln1_g, ln1_b, p_un, 1e-5f);

    // 2) means (commuted ahead of the pooling projections)
    mean_over_x_kernel<<<NB * NGR, 256>>>(p_un, p_meany);
    mean_over_y_kernel<<<NB * NGR, 256>>>(p_un, p_meanx);

    // 3-6) pooled reducers + qk projections, x/y batched (z)
    gemm_dual(p_meanx, p_meany, Wx_in, Wy_in, p_p2, p_p2 + 131072,
              512, 256, 256, nullptr, nullptr, 0);
    gemm_dual(p_p2, p_p2 + 131072, Wx1, Wy1, p_hsm2, p_hsm2 + 524288,
              512, 1024, 256, bx1, by1, 1);
    gemm_dual(p_hsm2, p_hsm2 + 524288, Wx2, Wy2, p_ux, p_uy,
              512, 256, 1024, bx2, by2, 0);
    gemm_dual(p_ux, p_uy, Wqk_x, Wqk_y, p_qk2, p_qk2 + 524288,
              512, 1024, 256, nullptr, nullptr, 0);

    // 7) RoPE (x+y in one launch)
    rope2_kernel<<<2048, 256>>>(p_qk2, cos_x, sin_x, cos_y, sin_y, p_q2, p_k2);

    // 8) scores + softmax (x+y in one launch): att2[0]=kx, att2[1]=ky
    attn_kernel<<<64, 256>>>(p_q2, p_k2, p_att2);

    // 9) V projection with fused transpose -> vt (b,h,y, x*64+c)
    gemm_big_vmap(p_un, Wv, p_vt, ROWS_ALL, 512, 256);

    // 10) einsum1: per (b,h): k_y(128x128) @ vt(128x8192)
    gemm_big(p_att2 + 524288, p_vt, p_uphi, 128, 8192, 128,
             16384, 1048576, 1048576, NB * HEADS, nullptr, nullptr, 0);

    // 11) einsum2 (k_x along x) fused with GroupNorm
    einsum2_gn_kernel<<<NB * HEADS * NGR, 256>>>(p_att2, p_uphi, p_gn);

    // 12) u2 = gn @ Wm + bm + u
    gemm_big(p_gn, Wm, p_u2, ROWS_ALL, 256, 512, 0, 0, 0, 1, bm, u, 0);

    // 13) LN2
    ln_kernel<<<ROWS_ALL, 256>>>(p_u2, ln2_g, ln2_b, p_ln2, 1e-5f);

    // 14-15) final MLP + residual
    gemm_big(p_ln2, Wf1, p_hid, ROWS_ALL, 1024, 256, 0, 0, 0, 1, bf1, nullptr, 1);
    gemm_big(p_hid, Wf2, out, ROWS_ALL, 256, 1024, 0, 0, 0, 1, bf2, p_u2, 0);

    (void)in_sizes; (void)n_in; (void)out_size;
}

// round 5
// speedup vs baseline: 3.7237x; 1.1939x over previous
#include <cuda_runtime.h>
#include <cuda_bf16.h>
#include <math.h>
#include <stdint.h>

// ---------------------------------------------------------------------------
// FABlock2D on GB300. tf32 mma.sync GEMMs (4 warps, 64x64 warp tiles,
// cp.async 2-stage). einsum1 scatters transposed so einsum2 is also a tensor
// GEMM with fused GroupNorm epilogue. Attn split over 4x more blocks.
// ---------------------------------------------------------------------------

#define NB   4
#define NGR  128
#define DIMC 256
#define HEADS 8
#define DH   64
#define ROWS_ALL (NB*NGR*NGR)   // 65536

// ------------------------- scratch (device globals) ------------------------
//   un    [0,        16777216)   live steps 1-9
//   vt    [50331648, 83886080)   live steps 9-10
//   uphiT [0,        33554432)   live steps 10-11  (un dead)
//   gn    [33554432, 67108864)   live steps 11-12  (vt dead)
//   u2    [0,        16777216)   live 12-end       (uphiT dead)
//   ln2   [16777216, 33554432)   live step 13-14
//   hid   [33554432, 100663296)  live step 14-15   (gn dead)
#define UN_OFF    0L
#define VT_OFF    50331648L
#define UPHI_OFF  0L
#define GN_OFF    33554432L
#define U2_OFF    0L
#define LN2_OFF   16777216L
#define HID_OFF   33554432L
#define ARENA_ELEMS 100663296L

__device__ float g_arena[ARENA_ELEMS];
__device__ float g_meanx[512*256];
__device__ float g_meany[512*256];
__device__ float g_p2   [2*512*256];
__device__ float g_hsm2 [2*512*1024];
__device__ float g_ux   [512*256];
__device__ float g_uy   [512*256];
__device__ float g_qk2  [2*512*1024];
__device__ float g_q2   [2*262144];
__device__ float g_k2   [2*262144];
__device__ float g_att2 [2*524288];   // [0]=x (kx), [1]=y (ky)

// ------------------------------- helpers -----------------------------------
__device__ __forceinline__ float gelu_tanh(float x) {
    float x3 = x * x * x;
    return 0.5f * x * (1.0f + tanhf(0.7978845608028654f * (x + 0.044715f * x3)));
}
__device__ __forceinline__ uint32_t f2tf32(float x) {
    uint32_t r;
    asm("cvt.rna.tf32.f32 %0, %1;" : "=r"(r) : "f"(x));
    return r;
}
__device__ __forceinline__ void mma_tf32(float c[4], const uint32_t a[4], const uint32_t b[2]) {
    asm volatile(
        "mma.sync.aligned.m16n8k8.row.col.f32.tf32.tf32.f32 "
        "{%0,%1,%2,%3}, {%4,%5,%6,%7}, {%8,%9}, {%0,%1,%2,%3};\n"
        : "+f"(c[0]), "+f"(c[1]), "+f"(c[2]), "+f"(c[3])
        : "r"(a[0]), "r"(a[1]), "r"(a[2]), "r"(a[3]), "r"(b[0]), "r"(b[1]));
}
__device__ __forceinline__ void cp16(void* dst, const void* src) {
    uint32_t d = (uint32_t)__cvta_generic_to_shared(dst);
    asm volatile("cp.async.ca.shared.global [%0], [%1], 16;\n" :: "r"(d), "l"(src));
}

// --------------------- pipelined tf32 tensor-core GEMM ----------------------
template<int BM, int BN, int BK>
struct GemmSmem {
    float As[2][BM][BK + 4];
    float Bs[2][BK][BN + 8];
};

// EPI: 0 normal (+bias/gelu/res), 1 = V scatter, 2 = einsum1 transpose scatter,
//      3 = einsum2 GroupNorm epilogue.
template<int BM, int BN, int BK, int THREADS, int WARPS_M, int WARPS_N, int EPI>
__device__ __forceinline__ void gemm_core(
        const float* __restrict__ A, const float* __restrict__ B, float* __restrict__ C,
        int M, int N, int K, int zb,
        const float* __restrict__ bias, const float* __restrict__ res, int do_gelu,
        GemmSmem<BM, BN, BK>& sm) {
    constexpr int WM = BM / WARPS_M;
    constexpr int WN = BN / WARPS_N;
    constexpr int MI = WM / 16;
    constexpr int NI = WN / 8;
    constexpr int ITA = (BM * BK / 4) / THREADS;
    constexpr int ITB = (BK * BN / 4) / THREADS;

    int tid = threadIdx.x;
    int warp = tid >> 5, lane = tid & 31;
    int wm = warp / WARPS_N, wn = warp % WARPS_N;
    int m0 = blockIdx.y * BM, n0 = blockIdx.x * BN;
    int lg = lane >> 2, lt = lane & 3;

    float c[MI][NI][4] = {};

    auto load_stage = [&](int k0, int s) {
        #pragma unroll
        for (int it = 0; it < ITA; it++) {
            int v = tid + it * THREADS;
            int m = v / (BK / 4), kq = (v % (BK / 4)) * 4;
            cp16(&sm.As[s][m][kq], A + (long)(m0 + m) * K + k0 + kq);
        }
        #pragma unroll
        for (int it = 0; it < ITB; it++) {
            int v = tid + it * THREADS;
            int k = v / (BN / 4), nq = (v % (BN / 4)) * 4;
            cp16(&sm.Bs[s][k][nq], B + (long)(k0 + k) * N + n0 + nq);
        }
    };

    int T = K / BK;
    load_stage(0, 0);
    asm volatile("cp.async.commit_group;\n");
    for (int t = 0; t < T; t++) {
        int cur = t & 1;
        if (t + 1 < T) load_stage((t + 1) * BK, cur ^ 1);
        asm volatile("cp.async.commit_group;\n");
        asm volatile("cp.async.wait_group 1;\n");
        __syncthreads();
        #pragma unroll
        for (int ks = 0; ks < BK / 8; ks++) {
            int kb = ks * 8;
            uint32_t af[MI][4], bf[NI][2];
            #pragma unroll
            for (int mi = 0; mi < MI; mi++) {
                int mr = wm * WM + mi * 16 + lg;
                af[mi][0] = f2tf32(sm.As[cur][mr][kb + lt]);
                af[mi][1] = f2tf32(sm.As[cur][mr + 8][kb + lt]);
                af[mi][2] = f2tf32(sm.As[cur][mr][kb + lt + 4]);
                af[mi][3] = f2tf32(sm.As[cur][mr + 8][kb + lt + 4]);
            }
            #pragma unroll
            for (int ni = 0; ni < NI; ni++) {
                int nc = wn * WN + ni * 8 + lg;
                bf[ni][0] = f2tf32(sm.Bs[cur][kb + lt][nc]);
                bf[ni][1] = f2tf32(sm.Bs[cur][kb + lt + 4][nc]);
            }
            #pragma unroll
            for (int mi = 0; mi < MI; mi++)
                #pragma unroll
                for (int ni = 0; ni < NI; ni++)
                    mma_tf32(c[mi][ni], af[mi], bf[ni]);
        }
        __syncthreads();
    }

    if (EPI == 3) {
        // GroupNorm epilogue: warp col-span is WN=64 => exactly one i group.
        int b = zb >> 3, h = zb & 7;
        int i_idx = (n0 + wn * WN) >> 6;
        #pragma unroll
        for (int mi = 0; mi < MI; mi++) {
            #pragma unroll
            for (int half = 0; half < 2; half++) {
                float s = 0.f, s2 = 0.f;
                #pragma unroll
                for (int ni = 0; ni < NI; ni++) {
                    float v0 = c[mi][ni][half * 2 + 0];
                    float v1 = c[mi][ni][half * 2 + 1];
                    s += v0 + v1; s2 += v0 * v0 + v1 * v1;
                }
                s  += __shfl_xor_sync(0xffffffffu, s, 1);
                s  += __shfl_xor_sync(0xffffffffu, s, 2);
                s2 += __shfl_xor_sync(0xffffffffu, s2, 1);
                s2 += __shfl_xor_sync(0xffffffffu, s2, 2);
                float mean = s * (1.f / 64.f);
                float var = fmaxf(s2 * (1.f / 64.f) - mean * mean, 0.f);
                float r = rsqrtf(var + 1e-6f);
                int l = wm * WM + mi * 16 + lg + half * 8;
                float* op = C + ((long)((b * 128 + i_idx) * 128 + l)) * 512 + h * 64;
                #pragma unroll
                for (int ni = 0; ni < NI; ni++) {
                    float2 o;
                    o.x = (c[mi][ni][half * 2 + 0] - mean) * r;
                    o.y = (c[mi][ni][half * 2 + 1] - mean) * r;
                    *(float2*)(op + ni * 8 + 2 * lt) = o;
                }
            }
        }
        return;
    }
    if (EPI == 2) {
        // einsum1 transpose scatter: C[i][(m,c)] -> uphiT[m][(i*64+c)]
        int m_idx = (n0 + wn * WN) >> 6;
        #pragma unroll
        for (int mi = 0; mi < MI; mi++) {
            #pragma unroll
            for (int half = 0; half < 2; half++) {
                int i_row = m0 + wm * WM + mi * 16 + lg + half * 8;
                float* op = C + (long)m_idx * 8192 + (long)i_row * 64;
                #pragma unroll
                for (int ni = 0; ni < NI; ni++) {
                    float2 o;
                    o.x = c[mi][ni][half * 2 + 0];
                    o.y = c[mi][ni][half * 2 + 1];
                    *(float2*)(op + ni * 8 + 2 * lt) = o;
                }
            }
        }
        return;
    }

    #pragma unroll
    for (int mi = 0; mi < MI; mi++) {
        #pragma unroll
        for (int ni = 0; ni < NI; ni++) {
            int col = n0 + wn * WN + ni * 8 + 2 * lt;
            float b0 = 0.f, b1 = 0.f;
            if (EPI == 0 && bias) { b0 = bias[col]; b1 = bias[col + 1]; }
            #pragma unroll
            for (int half = 0; half < 2; half++) {
                long row = m0 + wm * WM + mi * 16 + lg + half * 8;
                float v0 = c[mi][ni][half * 2 + 0] + b0;
                float v1 = c[mi][ni][half * 2 + 1] + b1;
                if (EPI == 0 && do_gelu) { v0 = gelu_tanh(v0); v1 = gelu_tanh(v1); }
                if (EPI == 0 && res) {
                    v0 += res[row * (long)N + col];
                    v1 += res[row * (long)N + col + 1];
                }
                float2 o; o.x = v0; o.y = v1;
                if (EPI == 1) {
                    // row=(b*128+y)*128+x, col=h*64+c -> vt[((b*8+h)*128+y)*8192+x*64+c]
                    int bb = (int)(row >> 14), y = (int)(row >> 7) & 127, x = (int)row & 127;
                    int h = col >> 6, cc = col & 63;
                    long off = ((long)((bb * 8 + h) * 128 + y)) * 8192 + x * 64 + cc;
                    *(float2*)(C + off) = o;
                } else {
                    *(float2*)(C + row * (long)N + col) = o;
                }
            }
        }
    }
}

template<int BM, int BN, int BK, int THREADS, int WARPS_M, int WARPS_N, int EPI>
__global__ __launch_bounds__(THREADS) void gemm_pipe_kernel(
        const float* __restrict__ A, const float* __restrict__ B, float* __restrict__ C,
        int M, int N, int K, long sA, long sB, long sC,
        const float* __restrict__ bias, const float* __restrict__ res, int do_gelu) {
    __shared__ __align__(16) GemmSmem<BM, BN, BK> sm;
    gemm_core<BM, BN, BK, THREADS, WARPS_M, WARPS_N, EPI>(
        A + (long)blockIdx.z * sA, B + (long)blockIdx.z * sB, C + (long)blockIdx.z * sC,
        M, N, K, blockIdx.z, bias, res, do_gelu, sm);
}

// dual-pointer variant for the x/y small chains
template<int BM, int BN, int BK, int THREADS, int WARPS_M, int WARPS_N>
__global__ __launch_bounds__(THREADS) void gemm_dual_kernel(
        const float* __restrict__ A0, const float* __restrict__ A1,
        const float* __restrict__ B0, const float* __restrict__ B1,
        float* __restrict__ C0, float* __restrict__ C1,
        int M, int N, int K,
        const float* __restrict__ bias0, const float* __restrict__ bias1, int do_gelu) {
    __shared__ __align__(16) GemmSmem<BM, BN, BK> sm;
    bool z = blockIdx.z != 0;
    gemm_core<BM, BN, BK, THREADS, WARPS_M, WARPS_N, 0>(
        z ? A1 : A0, z ? B1 : B0, z ? C1 : C0, M, N, K, 0,
        z ? bias1 : bias0, nullptr, do_gelu, sm);
}

// -------------------------------- LayerNorm --------------------------------
__global__ void ln_kernel(const float* __restrict__ x, const float* __restrict__ g,
                          const float* __restrict__ b, float* __restrict__ y, float eps) {
    long row = blockIdx.x;
    int t = threadIdx.x;
    float v = x[row * 256 + t];
    float s = v, s2 = v * v;
    #pragma unroll
    for (int o = 16; o; o >>= 1) {
        s  += __shfl_xor_sync(0xffffffffu, s,  o);
        s2 += __shfl_xor_sync(0xffffffffu, s2, o);
    }
    __shared__ float ws[8], ws2[8];
    int w = t >> 5, l = t & 31;
    if (l == 0) { ws[w] = s; ws2[w] = s2; }
    __syncthreads();
    if (w == 0) {
        float a  = (l < 8) ? ws[l]  : 0.f;
        float a2 = (l < 8) ? ws2[l] : 0.f;
        #pragma unroll
        for (int o = 4; o; o >>= 1) {
            a  += __shfl_xor_sync(0xffffffffu, a,  o);
            a2 += __shfl_xor_sync(0xffffffffu, a2, o);
        }
        if (l == 0) { ws[0] = a; ws2[0] = a2; }
    }
    __syncthreads();
    float mean = ws[0] * (1.f / 256.f);
    float var  = ws2[0] * (1.f / 256.f) - mean * mean;
    float r = rsqrtf(var + eps);
    y[row * 256 + t] = (v - mean) * r * g[t] + b[t];
}

// ------------------------- means over x / over y ----------------------------
__global__ void mean_over_x_kernel(const float* __restrict__ un, float* __restrict__ out) {
    int by = blockIdx.x;
    int c = threadIdx.x;
    const float* base = un + (long)by * NGR * DIMC + c;
    float s = 0.f;
    #pragma unroll 4
    for (int x = 0; x < NGR; x++) s += base[(long)x * DIMC];
    out[(long)by * DIMC + c] = s * (1.f / (float)NGR);
}
__global__ void mean_over_y_kernel(const float* __restrict__ un, float* __restrict__ out) {
    int bx = blockIdx.x;
    int b = bx >> 7, x = bx & 127;
    int c = threadIdx.x;
    const float* base = un + ((long)b * NGR * NGR + x) * DIMC + c;
    float s = 0.f;
    #pragma unroll 4
    for (int y = 0; y < NGR; y++) s += base[(long)y * NGR * DIMC];
    out[(long)bx * DIMC + c] = s * (1.f / (float)NGR);
}

// ------------------------------ RoPE (x+y) ----------------------------------
__global__ void rope2_kernel(const float* __restrict__ qk2,
                             const float* __restrict__ cx, const float* __restrict__ sx,
                             const float* __restrict__ cy, const float* __restrict__ sy,
                             float* __restrict__ q2, float* __restrict__ k2) {
    int idx = blockIdx.x * 256 + threadIdx.x;
    int z = idx >> 18;
    int i = idx & 262143;
    int d = i & 63;
    int n = (i >> 6) & 127;
    int h = (i >> 13) & 7;
    int b = i >> 16;
    const float* P = qk2 + (long)z * 524288 + (long)(b * 128 + n) * 1024;
    const float* cosv = z ? cy : cx;
    const float* sinv = z ? sy : sx;
    float c = cosv[n * 64 + d], s = sinv[n * 64 + d];
    int col = h * 64 + d;
    float t  = P[col];
    float rt = (d < 32) ? -P[col + 32] : P[col - 32];
    q2[idx] = t * c + rt * s;
    float t2  = P[512 + col];
    float rt2 = (d < 32) ? -P[512 + col + 32] : P[512 + col - 32];
    k2[idx] = t2 * c + rt2 * s;
}

// ----------------------- attention scores + softmax -------------------------
// grid (64, 4): (z,b,h) x 32-row slice. Interleaved col mapping (stride 16).
__global__ void attn_kernel(const float* __restrict__ q, const float* __restrict__ k,
                            float* __restrict__ attn) {
    __shared__ float qT[64 * 32];    // [d][r]
    __shared__ float kT[64 * 128];   // [d][c]
    int bh = blockIdx.x;
    int quarter = blockIdx.y;
    const float* qb = q + (long)bh * 8192 + quarter * 2048;
    const float* kb = k + (long)bh * 8192;
    int tid = threadIdx.x;
    for (int t = tid; t < 8192; t += 256) {
        int n = t >> 6, d = t & 63;
        kT[d * 128 + n] = kb[t];
    }
    for (int t = tid; t < 2048; t += 256) {
        int n = t >> 6, d = t & 63;
        qT[d * 32 + n] = qb[t];
    }
    __syncthreads();
    int r = tid >> 3;            // 0..31
    int c0 = (tid & 7) * 2;      // cols c0+16j, c0+1+16j
    float acc[16] = {};
    #pragma unroll 8
    for (int d = 0; d < 64; d++) {
        float qv = qT[d * 32 + r];
        #pragma unroll
        for (int j = 0; j < 8; j++) {
            acc[2 * j]     += qv * kT[d * 128 + c0 + 16 * j];
            acc[2 * j + 1] += qv * kT[d * 128 + c0 + 1 + 16 * j];
        }
    }
    float mx = -1e30f;
    #pragma unroll
    for (int j = 0; j < 16; j++) { acc[j] *= (1.f / 64.f); mx = fmaxf(mx, acc[j]); }
    #pragma unroll
    for (int o = 1; o < 8; o <<= 1) mx = fmaxf(mx, __shfl_xor_sync(0xffffffffu, mx, o));
    float s = 0.f;
    #pragma unroll
    for (int j = 0; j < 16; j++) { acc[j] = __expf(acc[j] - mx); s += acc[j]; }
    #pragma unroll
    for (int o = 1; o < 8; o <<= 1) s += __shfl_xor_sync(0xffffffffu, s, o);
    float inv = 1.f / s;
    float* op = attn + (long)bh * 16384 + (long)(quarter * 32 + r) * 128;
    #pragma unroll
    for (int j = 0; j < 8; j++) {
        float2 o; o.x = acc[2 * j] * inv; o.y = acc[2 * j + 1] * inv;
        *(float2*)(op + c0 + 16 * j) = o;
    }
}

// ------------------------------- host side ----------------------------------
static inline void gemm_big(const float* A, const float* B, float* C,
                            int M, int N, int K, long sA, long sB, long sC, int batch,
                            const float* bias, const float* res, int do_gelu) {
    dim3 grid(N / 128, M / 128, batch);
    gemm_pipe_kernel<128, 128, 16, 128, 2, 2, 0><<<grid, 128>>>(
        A, B, C, M, N, K, sA, sB, sC, bias, res, do_gelu);
}
template<int EPI>
static inline void gemm_big_epi(const float* A, const float* B, float* C,
                                int M, int N, int K, long sA, long sB, long sC, int batch) {
    dim3 grid(N / 128, M / 128, batch);
    gemm_pipe_kernel<128, 128, 16, 128, 2, 2, EPI><<<grid, 128>>>(
        A, B, C, M, N, K, sA, sB, sC, nullptr, nullptr, 0);
}
static inline void gemm_dual(const float* A0, const float* A1,
                             const float* B0, const float* B1,
                             float* C0, float* C1, int M, int N, int K,
                             const float* bias0, const float* bias1, int do_gelu) {
    dim3 grid(N / 64, M / 64, 2);
    gemm_dual_kernel<64, 64, 32, 128, 2, 2><<<grid, 128>>>(
        A0, A1, B0, B1, C0, C1, M, N, K, bias0, bias1, do_gelu);
}

extern "C" void kernel_launch(void* const* d_in, const int* in_sizes, int n_in,
                              void* d_out, int out_size) {
    const float* u      = (const float*)d_in[0];
    const float* cos_y  = (const float*)d_in[1];
    const float* sin_y  = (const float*)d_in[2];
    const float* cos_x  = (const float*)d_in[3];
    const float* sin_x  = (const float*)d_in[4];
    // d_in[5] scalar_cond: unused by reference
    const float* ln1_g  = (const float*)d_in[6];
    const float* ln1_b  = (const float*)d_in[7];
    const float* ln2_g  = (const float*)d_in[8];
    const float* ln2_b  = (const float*)d_in[9];
    const float* Wv     = (const float*)d_in[10];
    const float* Wy_in  = (const float*)d_in[11];
    const float* Wy1    = (const float*)d_in[12];
    const float* by1    = (const float*)d_in[13];
    const float* Wy2    = (const float*)d_in[14];
    const float* by2    = (const float*)d_in[15];
    const float* Wx_in  = (const float*)d_in[16];
    const float* Wx1    = (const float*)d_in[17];
    const float* bx1    = (const float*)d_in[18];
    const float* Wx2    = (const float*)d_in[19];
    const float* bx2    = (const float*)d_in[20];
    const float* Wqk_x  = (const float*)d_in[21];
    const float* Wqk_y  = (const float*)d_in[22];
    const float* Wm     = (const float*)d_in[23];
    const float* bm     = (const float*)d_in[24];
    const float* Wf1    = (const float*)d_in[25];
    const float* bf1    = (const float*)d_in[26];
    const float* Wf2    = (const float*)d_in[27];
    const float* bf2    = (const float*)d_in[28];
    float* out = (float*)d_out;

    float *arena, *p_meanx, *p_meany, *p_p2, *p_hsm2, *p_ux, *p_uy, *p_qk2;
    float *p_q2, *p_k2, *p_att2;
    cudaGetSymbolAddress((void**)&arena, g_arena);
    cudaGetSymbolAddress((void**)&p_meanx, g_meanx);
    cudaGetSymbolAddress((void**)&p_meany, g_meany);
    cudaGetSymbolAddress((void**)&p_p2, g_p2);
    cudaGetSymbolAddress((void**)&p_hsm2, g_hsm2);
    cudaGetSymbolAddress((void**)&p_ux, g_ux);
    cudaGetSymbolAddress((void**)&p_uy, g_uy);
    cudaGetSymbolAddress((void**)&p_qk2, g_qk2);
    cudaGetSymbolAddress((void**)&p_q2, g_q2);
    cudaGetSymbolAddress((void**)&p_k2, g_k2);
    cudaGetSymbolAddress((void**)&p_att2, g_att2);

    float* p_un    = arena + UN_OFF;
    float* p_vt    = arena + VT_OFF;
    float* p_uphiT = arena + UPHI_OFF;
    float* p_gn    = arena + GN_OFF;
    float* p_u2    = arena + U2_OFF;
    float* p_ln2   = arena + LN2_OFF;
    float* p_hid   = arena + HID_OFF;

    // 1) LayerNorm 1
    ln_kernel<<<ROWS_ALL, 256>>>(u, ln1_g, ln1_b, p_un, 1e-5f);

    // 2) means (commuted ahead of the pooling projections)
    mean_over_x_kernel<<<NB * NGR, 256>>>(p_un, p_meany);
    mean_over_y_kernel<<<NB * NGR, 256>>>(p_un, p_meanx);

    // 3-6) pooled reducers + qk projections, x/y batched
    gemm_dual(p_meanx, p_meany, Wx_in, Wy_in, p_p2, p_p2 + 131072,
              512, 256, 256, nullptr, nullptr, 0);
    gemm_dual(p_p2, p_p2 + 131072, Wx1, Wy1, p_hsm2, p_hsm2 + 524288,
              512, 1024, 256, bx1, by1, 1);
    gemm_dual(p_hsm2, p_hsm2 + 524288, Wx2, Wy2, p_ux, p_uy,
              512, 256, 1024, bx2, by2, 0);
    gemm_dual(p_ux, p_uy, Wqk_x, Wqk_y, p_qk2, p_qk2 + 524288,
              512, 1024, 256, nullptr, nullptr, 0);

    // 7) RoPE (x+y in one launch)
    rope2_kernel<<<2048, 256>>>(p_qk2, cos_x, sin_x, cos_y, sin_y, p_q2, p_k2);

    // 8) scores + softmax: att2[0]=kx, att2[1]=ky
    {
        dim3 g(64, 4);
        attn_kernel<<<g, 256>>>(p_q2, p_k2, p_att2);
    }

    // 9) V projection fused with transpose -> vt (b,h,y, x*64+c)
    gemm_big_epi<1>(p_un, Wv, p_vt, ROWS_ALL, 512, 256, 0, 0, 0, 1);

    // 10) einsum1 (k_y) with transpose scatter -> uphiT[(b,h,m), i*64+c]
    gemm_big_epi<2>(p_att2 + 524288, p_vt, p_uphiT, 128, 8192, 128,
                    16384, 1048576, 1048576, NB * HEADS);

    // 11) einsum2 (k_x) with fused GroupNorm -> gn[(b,i,l), h*64+c]
    gemm_big_epi<3>(p_att2, p_uphiT, p_gn, 128, 8192, 128,
                    16384, 1048576, 0, NB * HEADS);

    // 12) u2 = gn @ Wm + bm + u
    gemm_big(p_gn, Wm, p_u2, ROWS_ALL, 256, 512, 0, 0, 0, 1, bm, u, 0);

    // 13) LN2
    ln_kernel<<<ROWS_ALL, 256>>>(p_u2, ln2_g, ln2_b, p_ln2, 1e-5f);

    // 14-15) final MLP + residual
    gemm_big(p_ln2, Wf1, p_hid, ROWS_ALL, 1024, 256, 0, 0, 0, 1, bf1, nullptr, 1);
    gemm_big(p_hid, Wf2, out, ROWS_ALL, 256, 1024, 0, 0, 0, 1, bf2, p_u2, 0);

    (void)in_sizes; (void)n_in; (void)out_size;
}